// round 4
// baseline (speedup 1.0000x reference)
#include <cuda_runtime.h>

#define NMAX 100000
#define EMAX 1600000
#define H 64
#define EDIM 9
#define NEG_SLOPE 0.2f

// ---------------- scratch (device globals; allocation-free) ----------------
__device__ __align__(16) float g_h[(size_t)NMAX * H];    // h = x @ W
__device__ __align__(16) float g_out[(size_t)NMAX * H];  // UNNORMALIZED segment sum
__device__ __align__(16) float g_nd[(size_t)NMAX * 4];   // {denom, aesum, deg, pad}
__device__ float g_asrc[NMAX];
__device__ float g_adst[NMAX];
__device__ float g_alpha[EMAX];                          // exp(leaky(alpha)), unnormalized
__device__ float g_exloop[NMAX];
__device__ float g_p[NMAX];

// K1: per-node h = x @ W, a_src, a_dst. Warp per node.
// Also zeroes g_out row + g_nd entry (replaces both memsets; k1 precedes all users).
__global__ void k1_nodes(const float* __restrict__ x, const float* __restrict__ W,
                         const float* __restrict__ att_src,
                         const float* __restrict__ att_dst, int n) {
    __shared__ float sW[16 * H];
    for (int t = threadIdx.x; t < 16 * H; t += blockDim.x) sW[t] = W[t];
    __syncthreads();
    int node = (int)((blockIdx.x * (unsigned)blockDim.x + threadIdx.x) >> 5);
    int lane = threadIdx.x & 31;
    if (node >= n) return;
    // zero accumulators
    *(float2*)&g_out[(size_t)node * H + 2 * lane] = make_float2(0.f, 0.f);
    if (lane == 0) *(float4*)&g_nd[(size_t)node * 4] = make_float4(0.f, 0.f, 0.f, 0.f);
    float xv = (lane < 16) ? x[(size_t)node * 16 + lane] : 0.f;
    float h0 = 0.f, h1 = 0.f;
    #pragma unroll
    for (int k = 0; k < 16; k++) {
        float xk = __shfl_sync(0xffffffffu, xv, k);
        h0 += xk * sW[k * H + 2 * lane];
        h1 += xk * sW[k * H + 2 * lane + 1];
    }
    *(float2*)&g_h[(size_t)node * H + 2 * lane] = make_float2(h0, h1);
    float ps = h0 * att_src[2 * lane] + h1 * att_src[2 * lane + 1];
    float pd = h0 * att_dst[2 * lane] + h1 * att_dst[2 * lane + 1];
    #pragma unroll
    for (int o = 16; o > 0; o >>= 1) {
        ps += __shfl_xor_sync(0xffffffffu, ps, o);
        pd += __shfl_xor_sync(0xffffffffu, pd, o);
    }
    if (lane == 0) { g_asrc[node] = ps; g_adst[node] = pd; }
}

// K2: per edge: a_edge = ea.w_e ; alpha = exp(leaky(a_src+a_dst+a_edge));
//     one red.v4 accumulates {exp, a_edge, 1, 0} into g_nd[dst].
__global__ void k2_edges(const float* __restrict__ ea,
                         const int* __restrict__ src,
                         const int* __restrict__ dst,
                         const float* __restrict__ W_edge,
                         const float* __restrict__ att_edge, int E) {
    __shared__ float sWE[EDIM];
    __shared__ __align__(16) float sEA[256 * EDIM];
    if (threadIdx.x < EDIM) {
        float s = 0.f;
        #pragma unroll
        for (int k = 0; k < H; k++) s += W_edge[threadIdx.x * H + k] * att_edge[k];
        sWE[threadIdx.x] = s;
    }
    int base = blockIdx.x * 256;
    int nE = min(256, E - base);
    const float* gea = ea + (size_t)base * EDIM;
    if (nE == 256) {
        const float4* g4 = (const float4*)gea;   // 9216B block: float4-aligned
        float4* s4 = (float4*)sEA;
        #pragma unroll
        for (int t = threadIdx.x; t < 576; t += 256) s4[t] = g4[t];
    } else {
        for (int t = threadIdx.x; t < nE * EDIM; t += 256) sEA[t] = gea[t];
    }
    __syncthreads();
    if (threadIdx.x >= nE) return;
    int e = base + threadIdx.x;
    const float* v = &sEA[threadIdx.x * EDIM];
    float aedge = 0.f;
    #pragma unroll
    for (int j = 0; j < EDIM; j++) aedge += v[j] * sWE[j];
    int s = src[e], d = dst[e];
    float a = g_asrc[s] + g_adst[d] + aedge;
    a = (a >= 0.f) ? a : NEG_SLOPE * a;
    float ex = __expf(a);          // unstabilized: alpha is O(1), exp is safe
    g_alpha[e] = ex;
    float* p = &g_nd[(size_t)d * 4];
    asm volatile("red.global.add.v4.f32 [%0], {%1, %2, %3, %4};"
                 :: "l"(p), "f"(ex), "f"(aedge), "f"(1.0f), "f"(0.0f)
                 : "memory");
}

// K3: per node: self-loop alpha from mean a_edge; finalize denom.
__global__ void k3_nodes(int n) {
    int i = blockIdx.x * blockDim.x + threadIdx.x;
    if (i >= n) return;
    float4 nd = *(float4*)&g_nd[(size_t)i * 4];   // {denom, aesum, deg, _}
    float aedge = nd.y / fmaxf(nd.z, 1.f);
    float a = g_asrc[i] + g_adst[i] + aedge;
    a = (a >= 0.f) ? a : NEG_SLOPE * a;
    float exl = __expf(a);
    g_exloop[i] = exl;
    g_nd[(size_t)i * 4] = nd.x + exl;             // final denom
}

// K5: message scatter, UNNORMALIZED: out[d] += h[s]*ex.  8 lanes/edge,
//     2x float4 per lane (ILP=2), grid-stride persistent.
__global__ void k5_msg(const int* __restrict__ src,
                       const int* __restrict__ dst, int E) {
    int total = E * 8;
    int stride = gridDim.x * blockDim.x;
    for (int t = blockIdx.x * blockDim.x + threadIdx.x; t < total; t += stride) {
        int e = t >> 3;
        int l = t & 7;
        int s = src[e], d = dst[e];
        float ax = g_alpha[e];
        const float4* hp = (const float4*)&g_h[(size_t)s * H + l * 8];
        float4 h0 = hp[0];
        float4 h1 = hp[1];
        float* p = &g_out[(size_t)d * H + l * 8];
        asm volatile("red.global.add.v4.f32 [%0], {%1, %2, %3, %4};"
                     :: "l"(p), "f"(h0.x * ax), "f"(h0.y * ax),
                        "f"(h0.z * ax), "f"(h0.w * ax) : "memory");
        asm volatile("red.global.add.v4.f32 [%0], {%1, %2, %3, %4};"
                     :: "l"(p + 4), "f"(h1.x * ax), "f"(h1.y * ax),
                        "f"(h1.z * ax), "f"(h1.w * ax) : "memory");
    }
}

// K6: per node: (acc + h*exloop)/denom + bias, relu, p = x2 . lin_w. Warp/node.
__global__ void k6_nodes(const float* __restrict__ bias,
                         const float* __restrict__ lin_w, int n) {
    int node = (int)((blockIdx.x * (unsigned)blockDim.x + threadIdx.x) >> 5);
    int lane = threadIdx.x & 31;
    if (node >= n) return;
    float inv = 1.f / (g_nd[(size_t)node * 4] + 1e-16f);
    float exl = g_exloop[node];
    float2 hv  = *(const float2*)&g_h[(size_t)node * H + 2 * lane];
    float2 acc = *(const float2*)&g_out[(size_t)node * H + 2 * lane];
    float v0 = fmaxf((acc.x + hv.x * exl) * inv + bias[2 * lane], 0.f);
    float v1 = fmaxf((acc.y + hv.y * exl) * inv + bias[2 * lane + 1], 0.f);
    float pp = v0 * lin_w[2 * lane] + v1 * lin_w[2 * lane + 1];
    #pragma unroll
    for (int o = 16; o > 0; o >>= 1)
        pp += __shfl_xor_sync(0xffffffffu, pp, o);
    if (lane == 0) g_p[node] = pp;
}

// K7: per original edge: sigmoid(0.5*(p[src]+p[dst]) + lin_b)
__global__ void k7_out(const int* __restrict__ src,
                       const int* __restrict__ dst,
                       const float* __restrict__ lin_b,
                       float* __restrict__ out, int E) {
    int e = blockIdx.x * blockDim.x + threadIdx.x;
    if (e >= E) return;
    float z = 0.5f * (g_p[src[e]] + g_p[dst[e]]) + lin_b[0];
    out[e] = 1.f / (1.f + __expf(-z));
}

extern "C" void kernel_launch(void* const* d_in, const int* in_sizes, int n_in,
                              void* d_out, int out_size) {
    const float* x        = (const float*)d_in[0];
    const float* ea       = (const float*)d_in[1];
    const float* W        = (const float*)d_in[2];
    const float* W_edge   = (const float*)d_in[3];
    const float* att_src  = (const float*)d_in[4];
    const float* att_dst  = (const float*)d_in[5];
    const float* att_edge = (const float*)d_in[6];
    const float* bias     = (const float*)d_in[7];
    const float* lin_w    = (const float*)d_in[8];
    const float* lin_b    = (const float*)d_in[9];
    const int*   ei       = (const int*)d_in[10];   // int32 (JAX x64 disabled)

    int n = in_sizes[0] / 16;
    int E = in_sizes[1] / EDIM;
    const int* src = ei;
    const int* dst = ei + E;

    int k5_blocks = (E * 8 + 255) / 256;
    if (k5_blocks > 2368) k5_blocks = 2368;   // 148 SMs * 16 CTAs, persistent

    k1_nodes<<<(n + 7) / 8, 256>>>(x, W, att_src, att_dst, n);
    k2_edges<<<(E + 255) / 256, 256>>>(ea, src, dst, W_edge, att_edge, E);
    k3_nodes<<<(n + 255) / 256, 256>>>(n);
    k5_msg  <<<k5_blocks, 256>>>(src, dst, E);
    k6_nodes<<<(n + 7) / 8, 256>>>(bias, lin_w, n);
    k7_out  <<<(E + 255) / 256, 256>>>(src, dst, lin_b, (float*)d_out, E);
}

// round 5
// speedup vs baseline: 1.2960x; 1.2960x over previous
#include <cuda_runtime.h>

#define NMAX 100000
#define EMAX 1600000
#define H 64
#define EDIM 9
#define NEG_SLOPE 0.2f
#define NB_MAX 512            // max #blocks in k3a scan (n<=131072)

// ---------------- scratch (device globals; allocation-free) ----------------
__device__ __align__(16) float g_h[(size_t)NMAX * H];     // h = x @ W
__device__ __align__(16) float2 g_dae[NMAX];              // {sum_exp, sum_aedge}
__device__ int   g_cnt[NMAX];                             // in-degree
__device__ int   g_rowstart[NMAX];                        // CSR row starts
__device__ int   g_partial[NB_MAX];                       // scan partials
__device__ float g_asrc[NMAX];
__device__ float g_adst[NMAX];
__device__ float g_exloop[NMAX];
__device__ float g_invden[NMAX];
__device__ float g_p[NMAX];
__device__ float g_alpha[EMAX];                           // exp(leaky(alpha))
__device__ int   g_ofs[EMAX];                             // slot within dst bin
__device__ __align__(16) int2 g_sorted[EMAX];             // {src, alpha_bits} CSR-ordered

// K1: per-node h = x @ W, a_src, a_dst; zero cnt + dae. Warp per node.
__global__ void k1_nodes(const float* __restrict__ x, const float* __restrict__ W,
                         const float* __restrict__ att_src,
                         const float* __restrict__ att_dst, int n) {
    __shared__ float sW[16 * H];
    for (int t = threadIdx.x; t < 16 * H; t += blockDim.x) sW[t] = W[t];
    __syncthreads();
    int node = (int)((blockIdx.x * (unsigned)blockDim.x + threadIdx.x) >> 5);
    int lane = threadIdx.x & 31;
    if (node >= n) return;
    if (lane == 0) { g_cnt[node] = 0; g_dae[node] = make_float2(0.f, 0.f); }
    float xv = (lane < 16) ? x[(size_t)node * 16 + lane] : 0.f;
    float h0 = 0.f, h1 = 0.f;
    #pragma unroll
    for (int k = 0; k < 16; k++) {
        float xk = __shfl_sync(0xffffffffu, xv, k);
        h0 += xk * sW[k * H + 2 * lane];
        h1 += xk * sW[k * H + 2 * lane + 1];
    }
    *(float2*)&g_h[(size_t)node * H + 2 * lane] = make_float2(h0, h1);
    float ps = h0 * att_src[2 * lane] + h1 * att_src[2 * lane + 1];
    float pd = h0 * att_dst[2 * lane] + h1 * att_dst[2 * lane + 1];
    #pragma unroll
    for (int o = 16; o > 0; o >>= 1) {
        ps += __shfl_xor_sync(0xffffffffu, ps, o);
        pd += __shfl_xor_sync(0xffffffffu, pd, o);
    }
    if (lane == 0) { g_asrc[node] = ps; g_adst[node] = pd; }
}

// K2: per edge: alpha = exp(leaky(a_src+a_dst+ea.w_e));
//     red.v2 {exp, aedge} into g_dae[dst]; ofs[e] = cnt[dst]++.
__global__ void k2_edges(const float* __restrict__ ea,
                         const int* __restrict__ src,
                         const int* __restrict__ dst,
                         const float* __restrict__ W_edge,
                         const float* __restrict__ att_edge, int E) {
    __shared__ float sWE[EDIM];
    __shared__ __align__(16) float sEA[256 * EDIM];
    if (threadIdx.x < EDIM) {
        float s = 0.f;
        #pragma unroll
        for (int k = 0; k < H; k++) s += W_edge[threadIdx.x * H + k] * att_edge[k];
        sWE[threadIdx.x] = s;
    }
    int base = blockIdx.x * 256;
    int nE = min(256, E - base);
    const float* gea = ea + (size_t)base * EDIM;
    if (nE == 256) {
        const float4* g4 = (const float4*)gea;   // 9216B block: float4-aligned
        float4* s4 = (float4*)sEA;
        #pragma unroll
        for (int t = threadIdx.x; t < 576; t += 256) s4[t] = g4[t];
    } else {
        for (int t = threadIdx.x; t < nE * EDIM; t += 256) sEA[t] = gea[t];
    }
    __syncthreads();
    if (threadIdx.x >= nE) return;
    int e = base + threadIdx.x;
    const float* v = &sEA[threadIdx.x * EDIM];
    float aedge = 0.f;
    #pragma unroll
    for (int j = 0; j < EDIM; j++) aedge += v[j] * sWE[j];
    int s = src[e], d = dst[e];
    float a = g_asrc[s] + g_adst[d] + aedge;
    a = (a >= 0.f) ? a : NEG_SLOPE * a;
    float ex = __expf(a);                 // unstabilized: alpha is O(1)
    g_alpha[e] = ex;
    float* p = (float*)&g_dae[d];
    asm volatile("red.global.add.v2.f32 [%0], {%1, %2};"
                 :: "l"(p), "f"(ex), "f"(aedge) : "memory");
    g_ofs[e] = atomicAdd(&g_cnt[d], 1);
}

// K3a: per-block sum of cnt -> g_partial[block]
__global__ void k3a_partials(int n) {
    __shared__ int s[256];
    int i = blockIdx.x * 256 + threadIdx.x;
    int v = (i < n) ? g_cnt[i] : 0;
    s[threadIdx.x] = v;
    __syncthreads();
    #pragma unroll
    for (int o = 128; o > 0; o >>= 1) {
        if (threadIdx.x < o) s[threadIdx.x] += s[threadIdx.x + o];
        __syncthreads();
    }
    if (threadIdx.x == 0) g_partial[blockIdx.x] = s[0];
}

// K3b: exclusive scan of block partials (single block).
__global__ void k3b_scan(int nb) {
    __shared__ int s[NB_MAX];
    int t = threadIdx.x;
    int v = (t < nb) ? g_partial[t] : 0;
    s[t] = v;
    __syncthreads();
    #pragma unroll
    for (int o = 1; o < NB_MAX; o <<= 1) {
        int add = (t >= o) ? s[t - o] : 0;
        __syncthreads();
        s[t] += add;
        __syncthreads();
    }
    if (t < nb) g_partial[t] = s[t] - v;   // exclusive
}

// K3c: per node: row_start = partial[blk] + intra-block exclusive prefix;
//      node epilogue: self-loop exp, inv denom.
__global__ void k3c_rowstart(int n) {
    __shared__ int s[256];
    int i = blockIdx.x * 256 + threadIdx.x;
    int c = (i < n) ? g_cnt[i] : 0;
    s[threadIdx.x] = c;
    __syncthreads();
    #pragma unroll
    for (int o = 1; o < 256; o <<= 1) {
        int add = (threadIdx.x >= o) ? s[threadIdx.x - o] : 0;
        __syncthreads();
        s[threadIdx.x] += add;
        __syncthreads();
    }
    if (i >= n) return;
    g_rowstart[i] = g_partial[blockIdx.x] + s[threadIdx.x] - c;
    float2 dae = g_dae[i];                       // {sum_exp, sum_aedge}
    float aedge = dae.y / fmaxf((float)c, 1.f);
    float a = g_asrc[i] + g_adst[i] + aedge;
    a = (a >= 0.f) ? a : NEG_SLOPE * a;
    float exl = __expf(a);
    g_exloop[i] = exl;
    g_invden[i] = 1.f / (dae.x + exl + 1e-16f);
}

// K4: bin edges into CSR order: sorted[row_start[d]+ofs] = {src, alpha_bits}
__global__ void k4_bin(const int* __restrict__ src,
                       const int* __restrict__ dst, int E) {
    int e = blockIdx.x * blockDim.x + threadIdx.x;
    if (e >= E) return;
    int d = dst[e];
    int pos = g_rowstart[d] + g_ofs[e];
    g_sorted[pos] = make_int2(src[e], __float_as_int(g_alpha[e]));
}

// K5: gather aggregation, warp per dst node, NO atomics. Fused epilogue
//     (self-loop, normalize, bias, relu, dot lin_w -> p).
__global__ void k5_agg(const float* __restrict__ bias,
                       const float* __restrict__ lin_w, int n) {
    int node = (int)((blockIdx.x * (unsigned)blockDim.x + threadIdx.x) >> 5);
    int lane = threadIdx.x & 31;
    if (node >= n) return;
    int start = g_rowstart[node];
    int cnt = g_cnt[node];
    float a0 = 0.f, b0 = 0.f, a1 = 0.f, b1 = 0.f;   // two float2 accumulators
    int i = 0;
    for (; i + 2 <= cnt; i += 2) {
        int2 e0 = g_sorted[start + i];
        int2 e1 = g_sorted[start + i + 1];
        float2 h0 = *(const float2*)&g_h[(size_t)e0.x * H + 2 * lane];
        float2 h1 = *(const float2*)&g_h[(size_t)e1.x * H + 2 * lane];
        float x0 = __int_as_float(e0.y);
        float x1 = __int_as_float(e1.y);
        a0 += h0.x * x0; b0 += h0.y * x0;
        a1 += h1.x * x1; b1 += h1.y * x1;
    }
    if (i < cnt) {
        int2 e0 = g_sorted[start + i];
        float2 h0 = *(const float2*)&g_h[(size_t)e0.x * H + 2 * lane];
        float x0 = __int_as_float(e0.y);
        a0 += h0.x * x0; b0 += h0.y * x0;
    }
    a0 += a1; b0 += b1;
    // epilogue
    float exl = g_exloop[node];
    float inv = g_invden[node];
    float2 ho = *(const float2*)&g_h[(size_t)node * H + 2 * lane];
    float v0 = fmaxf((a0 + ho.x * exl) * inv + bias[2 * lane], 0.f);
    float v1 = fmaxf((b0 + ho.y * exl) * inv + bias[2 * lane + 1], 0.f);
    float pp = v0 * lin_w[2 * lane] + v1 * lin_w[2 * lane + 1];
    #pragma unroll
    for (int o = 16; o > 0; o >>= 1)
        pp += __shfl_xor_sync(0xffffffffu, pp, o);
    if (lane == 0) g_p[node] = pp;
}

// K7: per original edge: sigmoid(0.5*(p[src]+p[dst]) + lin_b)
__global__ void k7_out(const int* __restrict__ src,
                       const int* __restrict__ dst,
                       const float* __restrict__ lin_b,
                       float* __restrict__ out, int E) {
    int e = blockIdx.x * blockDim.x + threadIdx.x;
    if (e >= E) return;
    float z = 0.5f * (g_p[src[e]] + g_p[dst[e]]) + lin_b[0];
    out[e] = 1.f / (1.f + __expf(-z));
}

extern "C" void kernel_launch(void* const* d_in, const int* in_sizes, int n_in,
                              void* d_out, int out_size) {
    const float* x        = (const float*)d_in[0];
    const float* ea       = (const float*)d_in[1];
    const float* W        = (const float*)d_in[2];
    const float* W_edge   = (const float*)d_in[3];
    const float* att_src  = (const float*)d_in[4];
    const float* att_dst  = (const float*)d_in[5];
    const float* att_edge = (const float*)d_in[6];
    const float* bias     = (const float*)d_in[7];
    const float* lin_w    = (const float*)d_in[8];
    const float* lin_b    = (const float*)d_in[9];
    const int*   ei       = (const int*)d_in[10];   // int32 (JAX x64 disabled)

    int n = in_sizes[0] / 16;
    int E = in_sizes[1] / EDIM;
    const int* src = ei;
    const int* dst = ei + E;
    int nb = (n + 255) / 256;                       // 391 for n=100000

    k1_nodes    <<<(n + 7) / 8, 256>>>(x, W, att_src, att_dst, n);
    k2_edges    <<<(E + 255) / 256, 256>>>(ea, src, dst, W_edge, att_edge, E);
    k3a_partials<<<nb, 256>>>(n);
    k3b_scan    <<<1, NB_MAX>>>(nb);
    k3c_rowstart<<<nb, 256>>>(n);
    k4_bin      <<<(E + 255) / 256, 256>>>(src, dst, E);
    k5_agg      <<<(n + 7) / 8, 256>>>(bias, lin_w, n);
    k7_out      <<<(E + 255) / 256, 256>>>(src, dst, lin_b, (float*)d_out, E);
}